// round 1
// baseline (speedup 1.0000x reference)
#include <cuda_runtime.h>

// ---------------------------------------------------------------------------
// BiLSTM: B=128, T=256, D=256, U=256, 2 layers, bidirectional, residual on
// layer 2, merge='ave'. All fp32.
//
// Pipeline (5 launches, all graph-capturable, no allocs):
//   1. gemm_xz(layer=0): xz = x @ W_l0 + b  (fw & bw via grid.z)
//   2. rec(layer=0):     persistent scan over T, writes g_out1
//   3. gemm_xz(layer=1): xz = out1 @ W_l1 + b
//   4. rec(layer=1):     writes g_out2
//   5. merge:            out = 0.5*(out2f+out1f+out2b+out1b)  (residual+ave)
// ---------------------------------------------------------------------------

#define T_LEN 256
#define U_DIM 256
#define B_DIM 128

// ---- scratch (device globals; allocation is forbidden) --------------------
__device__ float g_xz[2][33554432];     // [dir][(b*T+t)*1024 + col]   128MB x2
__device__ float g_out1[2][8388608];    // [dir][(b*T+t)*256 + u]
__device__ float g_out2[2][8388608];
__device__ float g_h[2][2][B_DIM * U_DIM];  // [dir][phase][b*256+u]
__device__ unsigned g_cnt[16];
__device__ volatile unsigned g_sns[16];

__device__ __forceinline__ float sigf(float x) {
    return 1.0f / (1.0f + __expf(-x));
}
__device__ __forceinline__ float tanhf_fast(float x) {
    return 2.0f / (1.0f + __expf(-2.0f * x)) - 1.0f;
}

// ---------------------------------------------------------------------------
// GEMM: C[M=32768, N=1024] = A[M,256] @ W[256,1024] + bias
// Tiles: BM=128, BN=64, BK=16, 256 threads, 8x4 per thread.
// grid = (16, 256, 2): z = direction.
// ---------------------------------------------------------------------------
__global__ __launch_bounds__(256) void gemm_xz_kernel(
    const float* __restrict__ x,
    const float* __restrict__ kfw, const float* __restrict__ kbw,
    const float* __restrict__ bfw, const float* __restrict__ bbw,
    int layer)
{
    const int dir = blockIdx.z;
    const float* __restrict__ A = (layer == 0) ? x : g_out1[dir];
    const float* __restrict__ W = (dir ? kbw : kfw) + layer * 262144;
    const float* __restrict__ bias = (dir ? bbw : bfw) + layer * 1024;
    float* __restrict__ C = g_xz[dir];

    const int m0 = blockIdx.y * 128;
    const int n0 = blockIdx.x * 64;

    __shared__ float As[16][132];
    __shared__ float Bs[16][68];

    const int tid = threadIdx.x;
    const int tx = tid & 15;          // col group: cols 4*tx..4*tx+3
    const int ty = tid >> 4;          // row group: rows 8*ty..8*ty+7
    const int ar = tid >> 2;          // A load row (0..63)
    const int ac = (tid & 3) << 2;    // A load col (0,4,8,12)
    const int br = tid >> 4;          // B load row (0..15)
    const int bc = (tid & 15) << 2;   // B load col

    float acc[8][4];
#pragma unroll
    for (int i = 0; i < 8; i++)
#pragma unroll
        for (int j = 0; j < 4; j++) acc[i][j] = 0.0f;

    for (int k0 = 0; k0 < 256; k0 += 16) {
        float4 a0 = *(const float4*)&A[(m0 + ar) * 256 + k0 + ac];
        float4 a1 = *(const float4*)&A[(m0 + ar + 64) * 256 + k0 + ac];
        float4 b0 = *(const float4*)&W[(k0 + br) * 1024 + n0 + bc];
        __syncthreads();
        As[ac + 0][ar] = a0.x; As[ac + 1][ar] = a0.y;
        As[ac + 2][ar] = a0.z; As[ac + 3][ar] = a0.w;
        As[ac + 0][ar + 64] = a1.x; As[ac + 1][ar + 64] = a1.y;
        As[ac + 2][ar + 64] = a1.z; As[ac + 3][ar + 64] = a1.w;
        *(float4*)&Bs[br][bc] = b0;
        __syncthreads();
#pragma unroll
        for (int kk = 0; kk < 16; kk++) {
            float4 aa0 = *(const float4*)&As[kk][ty * 8];
            float4 aa1 = *(const float4*)&As[kk][ty * 8 + 4];
            float4 bb  = *(const float4*)&Bs[kk][tx * 4];
            float a[8] = {aa0.x, aa0.y, aa0.z, aa0.w, aa1.x, aa1.y, aa1.z, aa1.w};
            float b[4] = {bb.x, bb.y, bb.z, bb.w};
#pragma unroll
            for (int i = 0; i < 8; i++)
#pragma unroll
                for (int j = 0; j < 4; j++) acc[i][j] += a[i] * b[j];
        }
    }

    float4 bv = *(const float4*)&bias[n0 + tx * 4];
#pragma unroll
    for (int i = 0; i < 8; i++) {
        float4 o;
        o.x = acc[i][0] + bv.x; o.y = acc[i][1] + bv.y;
        o.z = acc[i][2] + bv.z; o.w = acc[i][3] + bv.w;
        *(float4*)&C[(m0 + ty * 8 + i) * 1024 + n0 + tx * 4] = o;
    }
}

// ---------------------------------------------------------------------------
// Persistent recurrence kernel.
// 128 CTAs = 2 dirs x 8 batch-tiles(16 rows) x 8 gate-tiles(32 units x 4 gates)
// R slice (256x128, gate-interleaved) resident in SMEM. h exchanged via L2
// with double buffer + 8-CTA sense-reversing barrier per step.
// 128 threads: lane = col group (4 cols), warp w = row group (rows 4w..4w+3).
// ---------------------------------------------------------------------------
#define REC_SMEM_FLOATS (32768 + 5120 + 2176 + 544)
#define REC_SMEM_BYTES (REC_SMEM_FLOATS * 4)

__device__ __forceinline__ void group_barrier(int grp, unsigned* s_sense) {
    __syncthreads();
    if (threadIdx.x == 0) {
        unsigned ls = *s_sense ^ 1u;
        *s_sense = ls;
        __threadfence();
        unsigned v = atomicAdd(&g_cnt[grp], 1u);
        if (v == 7u) {
            g_cnt[grp] = 0u;
            __threadfence();
            g_sns[grp] = ls;
        } else {
            while (g_sns[grp] != ls) { }
        }
    }
    __syncthreads();
}

__global__ __launch_bounds__(128) void rec_kernel(
    const float* __restrict__ rfw, const float* __restrict__ rbw, int layer)
{
    extern __shared__ float sm[];
    float* Rs = sm;                // [256][128]
    float* hs = Rs + 32768;        // [256][20]  (k-major, padded)
    float* zs = hs + 5120;         // [128][17]  z exchange
    float* cs = zs + 2176;         // [32][17]   cell state

    const int bx  = blockIdx.x;
    const int dir = bx >> 6;
    const int gt  = bx & 7;
    const int grp = bx >> 3;            // dir*8 + batch_tile
    const int b0  = ((bx >> 3) & 7) * 16;
    const int u0  = gt * 32;

    const float* __restrict__ R   = (dir ? rbw : rfw) + layer * 262144;
    const float* __restrict__ xz  = g_xz[dir];
    float* __restrict__ outp      = layer ? g_out2[dir] : g_out1[dir];
    float* __restrict__ hbuf0     = g_h[dir][0];
    float* __restrict__ hbuf1     = g_h[dir][1];

    const int tid  = threadIdx.x;
    const int lane = tid & 31;
    const int w    = tid >> 5;

    __shared__ unsigned s_sense;
    if (tid == 0) s_sense = g_sns[grp];

    // Load R slice, permuted: col ci = q*32+uu  ->  original col q*256+u0+uu
    for (int idx = tid; idx < 256 * 128; idx += 128) {
        int k  = idx >> 7;
        int ci = idx & 127;
        int q  = ci >> 5;
        int uu = ci & 31;
        Rs[idx] = R[k * 1024 + q * 256 + u0 + uu];
    }

    // Init c = 0 (SMEM) and h phase0 = 0 (global, this CTA's slice)
    {
        int uu = lane;
#pragma unroll
        for (int j = 0; j < 4; j++) {
            int bi = 4 * w + j;
            cs[uu * 17 + bi] = 0.0f;
            hbuf0[(b0 + bi) * 256 + u0 + uu] = 0.0f;
        }
    }
    group_barrier(grp, &s_sense);

    // xz column base for this thread (permuted 4-col group)
    const int q   = lane >> 3;
    const int off = (lane & 7) * 4;
    const int gcol = q * 256 + u0 + off;

    for (int s = 0; s < 256; s++) {
        const int t = dir ? (255 - s) : s;
        const float* __restrict__ hprev = (s & 1) ? hbuf1 : hbuf0;
        float* __restrict__ hnext = (s & 1) ? hbuf0 : hbuf1;

        // Prefetch xz into accumulators (independent of h -> overlaps)
        float acc[4][4];
#pragma unroll
        for (int r = 0; r < 4; r++) {
            float4 v = *(const float4*)&xz[((b0 + 4 * w + r) * 256 + t) * 1024 + gcol];
            acc[r][0] = v.x; acc[r][1] = v.y; acc[r][2] = v.z; acc[r][3] = v.w;
        }

        // Load h tile (16x256) transposed into SMEM, L2-coherent loads
#pragma unroll
        for (int m = 0; m < 4; m++) {
            int bi = w + 4 * m;
            const float* src = hprev + (b0 + bi) * 256;
#pragma unroll
            for (int j = 0; j < 8; j++) {
                int k = lane + 32 * j;
                hs[k * 20 + bi] = __ldcg(src + k);
            }
        }
        __syncthreads();

        // z += h @ R_slice   (16x128x256)
#pragma unroll 4
        for (int k = 0; k < 256; k++) {
            float4 hv = *(const float4*)&hs[k * 20 + 4 * w];
            float4 rv = *(const float4*)&Rs[k * 128 + 4 * lane];
            acc[0][0] += hv.x * rv.x; acc[0][1] += hv.x * rv.y;
            acc[0][2] += hv.x * rv.z; acc[0][3] += hv.x * rv.w;
            acc[1][0] += hv.y * rv.x; acc[1][1] += hv.y * rv.y;
            acc[1][2] += hv.y * rv.z; acc[1][3] += hv.y * rv.w;
            acc[2][0] += hv.z * rv.x; acc[2][1] += hv.z * rv.y;
            acc[2][2] += hv.z * rv.z; acc[2][3] += hv.z * rv.w;
            acc[3][0] += hv.w * rv.x; acc[3][1] += hv.w * rv.y;
            acc[3][2] += hv.w * rv.z; acc[3][3] += hv.w * rv.w;
        }

        // Stash z to SMEM for gate regrouping
#pragma unroll
        for (int r = 0; r < 4; r++)
#pragma unroll
            for (int c = 0; c < 4; c++)
                zs[(4 * lane + c) * 17 + (4 * w + r)] = acc[r][c];
        __syncthreads();

        // Gate nonlinearities + state update (thread owns (uu=lane, 4 rows))
        {
            int uu = lane;
#pragma unroll
            for (int j = 0; j < 4; j++) {
                int bi = 4 * w + j;
                float zi = zs[(uu) * 17 + bi];
                float zf = zs[(32 + uu) * 17 + bi];
                float zg = zs[(64 + uu) * 17 + bi];
                float zo = zs[(96 + uu) * 17 + bi];
                float ig = sigf(zi);
                float fg = sigf(zf);
                float gg = tanhf_fast(zg);
                float og = sigf(zo);
                float cc = fg * cs[uu * 17 + bi] + ig * gg;
                cs[uu * 17 + bi] = cc;
                float hh = og * tanhf_fast(cc);
                hnext[(b0 + bi) * 256 + u0 + uu] = hh;
                outp[((b0 + bi) * 256 + t) * 256 + u0 + uu] = hh;
            }
        }
        group_barrier(grp, &s_sense);
    }
}

// ---------------------------------------------------------------------------
// Merge: out = 0.5 * (out2f + out1f + out2b + out1b)  (residual + average)
// ---------------------------------------------------------------------------
__global__ __launch_bounds__(256) void merge_kernel(float4* __restrict__ out) {
    int i = blockIdx.x * blockDim.x + threadIdx.x;   // 2097152 float4s
    const float4* a = (const float4*)g_out1[0];
    const float4* b = (const float4*)g_out2[0];
    const float4* c = (const float4*)g_out1[1];
    const float4* d = (const float4*)g_out2[1];
    float4 va = a[i], vb = b[i], vc = c[i], vd = d[i];
    float4 o;
    o.x = 0.5f * (va.x + vb.x + vc.x + vd.x);
    o.y = 0.5f * (va.y + vb.y + vc.y + vd.y);
    o.z = 0.5f * (va.z + vb.z + vc.z + vd.z);
    o.w = 0.5f * (va.w + vb.w + vc.w + vd.w);
    out[i] = o;
}

// ---------------------------------------------------------------------------
extern "C" void kernel_launch(void* const* d_in, const int* in_sizes, int n_in,
                              void* d_out, int out_size) {
    (void)in_sizes; (void)n_in; (void)out_size;
    const float* x   = (const float*)d_in[0];
    const float* kfw = (const float*)d_in[1];
    const float* rfw = (const float*)d_in[2];
    const float* bfw = (const float*)d_in[3];
    const float* kbw = (const float*)d_in[4];
    const float* rbw = (const float*)d_in[5];
    const float* bbw = (const float*)d_in[6];
    float* out = (float*)d_out;

    cudaFuncSetAttribute(rec_kernel,
                         cudaFuncAttributeMaxDynamicSharedMemorySize,
                         REC_SMEM_BYTES);

    dim3 gg(16, 256, 2);
    gemm_xz_kernel<<<gg, 256>>>(x, kfw, kbw, bfw, bbw, 0);
    rec_kernel<<<128, 128, REC_SMEM_BYTES>>>(rfw, rbw, 0);
    gemm_xz_kernel<<<gg, 256>>>(x, kfw, kbw, bfw, bbw, 1);
    rec_kernel<<<128, 128, REC_SMEM_BYTES>>>(rfw, rbw, 1);
    merge_kernel<<<8192, 256>>>((float4*)out);
}